// round 6
// baseline (speedup 1.0000x reference)
#include <cuda_runtime.h>

// DiffJPEG (32,3,512,512) fp32: per-8x8-block DCT -> quant/dequant -> IDCT.
// One thread per 8x8 block, register-resident, packed f32x2 ops.
// AAN 5-mul factored DCT; row scales folded into quant tables; inverse is the
// flow-graph transpose of the forward (verified numerically on the full basis).

typedef unsigned long long u64;

__device__ __forceinline__ u64 pk2(float lo, float hi) {
    u64 r; asm("mov.b64 %0, {%1, %2};" : "=l"(r) : "f"(lo), "f"(hi)); return r;
}
__device__ __forceinline__ float plo(u64 a) { return __uint_as_float((unsigned)a); }
__device__ __forceinline__ float phi(u64 a) { return __uint_as_float((unsigned)(a >> 32)); }

__device__ __forceinline__ u64 padd(u64 a, u64 b) {
    u64 r; asm("add.rn.f32x2 %0, %1, %2;" : "=l"(r) : "l"(a), "l"(b)); return r;
}
__device__ __forceinline__ u64 psub(u64 a, u64 b) {
    u64 r; asm("sub.rn.f32x2 %0, %1, %2;" : "=l"(r) : "l"(a), "l"(b)); return r;
}
__device__ __forceinline__ u64 pmul(u64 a, u64 b) {
    u64 r; asm("mul.rn.f32x2 %0, %1, %2;" : "=l"(r) : "l"(a), "l"(b)); return r;
}
__device__ __forceinline__ u64 pfma(u64 a, u64 b, u64 c) {
    u64 r; asm("fma.rn.f32x2 %0, %1, %2, %3;" : "=l"(r) : "l"(a), "l"(b), "l"(c)); return r;
}

// AAN constants (shared by forward and inverse).
#define Af 0.70710678118654752f
#define Bf 0.38268343236508977f
#define Cf 0.54119610014619698f
#define Ef 1.30656296487637653f

// AAN forward 8-pt (scaled DCT): y = diag(g) * D8 * x, g0=2sqrt2, gu=4cos(u*pi/16)
__device__ __forceinline__ void fdct8p(u64& x0, u64& x1, u64& x2, u64& x3,
                                       u64& x4, u64& x5, u64& x6, u64& x7,
                                       const u64* K) {
    u64 t0 = padd(x0, x7), t7 = psub(x0, x7);
    u64 t1 = padd(x1, x6), t6 = psub(x1, x6);
    u64 t2 = padd(x2, x5), t5 = psub(x2, x5);
    u64 t3 = padd(x3, x4), t4 = psub(x3, x4);
    u64 t10 = padd(t0, t3), t13 = psub(t0, t3);
    u64 t11 = padd(t1, t2), t12 = psub(t1, t2);
    x0 = padd(t10, t11);
    x4 = psub(t10, t11);
    u64 z1 = pmul(K[0], padd(t12, t13));
    x2 = padd(t13, z1);
    x6 = psub(t13, z1);
    u64 u10 = padd(t4, t5), u11 = padd(t5, t6), u12 = padd(t6, t7);
    u64 z5 = pmul(K[1], psub(u10, u12));
    u64 z2 = pfma(K[2], u10, z5);
    u64 z4 = pfma(K[3], u12, z5);
    u64 z3 = pmul(K[0], u11);
    u64 z11 = padd(t7, z3), z13 = psub(t7, z3);
    x5 = padd(z13, z2);
    x3 = psub(z13, z2);
    x1 = padd(z11, z4);
    x7 = psub(z11, z4);
}

// Transposed-graph inverse: x = D8^T * diag(g) * w  (g folded into dequant table).
__device__ __forceinline__ void idct8p(u64& w0, u64& w1, u64& w2, u64& w3,
                                       u64& w4, u64& w5, u64& w6, u64& w7,
                                       const u64* K) {
    // odd adjoints
    u64 z13 = padd(w5, w3);
    u64 z2  = psub(w5, w3);
    u64 z11 = padd(w1, w7);
    u64 z4  = psub(w1, w7);
    u64 t7b = padd(z11, z13);
    u64 u11 = pmul(K[0], psub(z11, z13));
    u64 z5  = padd(z4, z2);
    u64 tb  = pmul(K[1], z5);
    u64 u10 = pfma(K[2], z2, tb);
    u64 u12 = psub(pmul(K[3], z4), tb);
    u64 s4 = u10;
    u64 s5 = padd(u10, u11);
    u64 s6 = padd(u11, u12);
    u64 s7 = padd(t7b, u12);
    // even adjoints
    u64 z1  = psub(w2, w6);
    u64 t12 = pmul(K[0], z1);
    u64 t13 = padd(padd(w2, w6), t12);
    u64 t10 = padd(w0, w4);
    u64 t11 = psub(w0, w4);
    u64 s0 = padd(t10, t13);
    u64 s3 = psub(t10, t13);
    u64 s1 = padd(t11, t12);
    u64 s2 = psub(t11, t12);
    // final butterflies
    w0 = padd(s0, s7);  w7 = psub(s0, s7);
    w1 = padd(s1, s6);  w6 = psub(s1, s6);
    w2 = padd(s2, s5);  w5 = psub(s2, s5);
    w3 = padd(s3, s4);  w4 = psub(s3, s4);
}

// 2x2 element-block transpose across two packed regs.
__device__ __forceinline__ void tr2(u64& x0, u64& x1) {
    u64 y0 = pk2(plo(x0), plo(x1));
    u64 y1 = pk2(phi(x0), phi(x1));
    x0 = y0; x1 = y1;
}

// In-place 8x8 element transpose of A[8][4] packed state.
__device__ __forceinline__ void repack(u64 A[8][4]) {
#pragma unroll
    for (int a = 0; a < 4; a++) {
        tr2(A[2 * a][a], A[2 * a + 1][a]);
#pragma unroll
        for (int b = a + 1; b < 4; b++) {
            u64 p0 = A[2 * a][b], p1 = A[2 * a + 1][b];
            u64 q0 = A[2 * b][a], q1 = A[2 * b + 1][a];
            tr2(p0, p1); tr2(q0, q1);
            A[2 * a][b] = q0; A[2 * a + 1][b] = q1;
            A[2 * b][a] = p0; A[2 * b + 1][a] = p1;
        }
    }
}

// AAN row scales: g0 = 2*sqrt(2), gu = 4*cos(u*pi/16).
static constexpr float G0f = 2.82842712474619010f;
static constexpr float G1f = 3.92314112161292954f;
static constexpr float G2f = 3.69551813004514864f;
static constexpr float G3f = 3.32587844920940013f;
static constexpr float G4f = 2.82842712474619010f;
static constexpr float G5f = 2.22228093207667189f;
static constexpr float G6f = 1.53073372946035862f;
static constexpr float G7f = 0.78036128806451527f;

#define FI(u,v,q) (1.0f / (G##u##f * G##v##f * q))
#define FV(u,v,q) (q / (G##u##f * G##v##f))

// Tables indexed [j*4 + q] = {f(u=2q, v=j), f(u=2q+1, v=j)} — same layout as the
// verified R4 tables, with the AAN g_u*g_v fold applied per element.
static __device__ __constant__ float2 kQi2[32] = {
    {FI(0,0,16.f),FI(1,0,12.f)},{FI(2,0,14.f),FI(3,0,14.f)},{FI(4,0,18.f),FI(5,0,24.f)},{FI(6,0,49.f),FI(7,0,72.f)},
    {FI(0,1,11.f),FI(1,1,12.f)},{FI(2,1,13.f),FI(3,1,17.f)},{FI(4,1,22.f),FI(5,1,35.f)},{FI(6,1,64.f),FI(7,1,92.f)},
    {FI(0,2,10.f),FI(1,2,14.f)},{FI(2,2,16.f),FI(3,2,22.f)},{FI(4,2,37.f),FI(5,2,55.f)},{FI(6,2,78.f),FI(7,2,95.f)},
    {FI(0,3,16.f),FI(1,3,19.f)},{FI(2,3,24.f),FI(3,3,29.f)},{FI(4,3,56.f),FI(5,3,64.f)},{FI(6,3,87.f),FI(7,3,98.f)},
    {FI(0,4,24.f),FI(1,4,26.f)},{FI(2,4,40.f),FI(3,4,51.f)},{FI(4,4,68.f),FI(5,4,81.f)},{FI(6,4,103.f),FI(7,4,112.f)},
    {FI(0,5,40.f),FI(1,5,58.f)},{FI(2,5,57.f),FI(3,5,87.f)},{FI(4,5,109.f),FI(5,5,104.f)},{FI(6,5,121.f),FI(7,5,100.f)},
    {FI(0,6,51.f),FI(1,6,60.f)},{FI(2,6,69.f),FI(3,6,80.f)},{FI(4,6,103.f),FI(5,6,113.f)},{FI(6,6,120.f),FI(7,6,103.f)},
    {FI(0,7,61.f),FI(1,7,55.f)},{FI(2,7,56.f),FI(3,7,62.f)},{FI(4,7,77.f),FI(5,7,92.f)},{FI(6,7,101.f),FI(7,7,99.f)}
};
static __device__ __constant__ float2 kQv2[32] = {
    {FV(0,0,16.f),FV(1,0,12.f)},{FV(2,0,14.f),FV(3,0,14.f)},{FV(4,0,18.f),FV(5,0,24.f)},{FV(6,0,49.f),FV(7,0,72.f)},
    {FV(0,1,11.f),FV(1,1,12.f)},{FV(2,1,13.f),FV(3,1,17.f)},{FV(4,1,22.f),FV(5,1,35.f)},{FV(6,1,64.f),FV(7,1,92.f)},
    {FV(0,2,10.f),FV(1,2,14.f)},{FV(2,2,16.f),FV(3,2,22.f)},{FV(4,2,37.f),FV(5,2,55.f)},{FV(6,2,78.f),FV(7,2,95.f)},
    {FV(0,3,16.f),FV(1,3,19.f)},{FV(2,3,24.f),FV(3,3,29.f)},{FV(4,3,56.f),FV(5,3,64.f)},{FV(6,3,87.f),FV(7,3,98.f)},
    {FV(0,4,24.f),FV(1,4,26.f)},{FV(2,4,40.f),FV(3,4,51.f)},{FV(4,4,68.f),FV(5,4,81.f)},{FV(6,4,103.f),FV(7,4,112.f)},
    {FV(0,5,40.f),FV(1,5,58.f)},{FV(2,5,57.f),FV(3,5,87.f)},{FV(4,5,109.f),FV(5,5,104.f)},{FV(6,5,121.f),FV(7,5,100.f)},
    {FV(0,6,51.f),FV(1,6,60.f)},{FV(2,6,69.f),FV(3,6,80.f)},{FV(4,6,103.f),FV(5,6,113.f)},{FV(6,6,120.f),FV(7,6,103.f)},
    {FV(0,7,61.f),FV(1,7,55.f)},{FV(2,7,56.f),FV(3,7,62.f)},{FV(4,7,77.f),FV(5,7,92.f)},{FV(6,7,101.f),FV(7,7,99.f)}
};

static constexpr int kNumBlocks = 32 * 3 * 64 * 64;   // 393216

__global__ __launch_bounds__(128, 6)
void diffjpeg_kernel(const float* __restrict__ in, float* __restrict__ out) {
    unsigned t = blockIdx.x * 128u + threadIdx.x;

    unsigned bc  = t & 63u;
    unsigned br  = (t >> 6) & 63u;
    unsigned img = t >> 12;
    unsigned off = (img << 18) + (br << 12) + (bc << 3);   // elements

    const float* p = in + off;
    float* qo = out + off;

    u64 K[4];
    K[0] = pk2(Af, Af); K[1] = pk2(Bf, Bf);
    K[2] = pk2(Cf, Cf); K[3] = pk2(Ef, Ef);
    const u64 MAG = pk2(12582912.0f, 12582912.0f);   // 1.5 * 2^23

    // State: A[r][p] = {x[r][2p], x[r][2p+1]} (column-pair packing).
    u64 A[8][4];
#pragma unroll
    for (int r = 0; r < 8; r++) {
        ulonglong2 a = *reinterpret_cast<const ulonglong2*>(p + r * 512);
        ulonglong2 b = *reinterpret_cast<const ulonglong2*>(p + r * 512 + 4);
        A[r][0] = a.x; A[r][1] = a.y; A[r][2] = b.x; A[r][3] = b.y;
    }

    // Column DCT (combine over r).
#pragma unroll
    for (int c = 0; c < 4; c++)
        fdct8p(A[0][c], A[1][c], A[2][c], A[3][c], A[4][c], A[5][c], A[6][c], A[7][c], K);

    repack(A);   // -> row-pair packing

    // Row DCT.
#pragma unroll
    for (int c = 0; c < 4; c++)
        fdct8p(A[0][c], A[1][c], A[2][c], A[3][c], A[4][c], A[5][c], A[6][c], A[7][c], K);

    // Quantize (fused fma + magic RNE) and dequantize; AAN scales folded in tables.
#pragma unroll
    for (int j = 0; j < 8; j++) {
#pragma unroll
        for (int q = 0; q < 4; q++) {
            u64 qi = *reinterpret_cast<const u64*>(&kQi2[j * 4 + q]);
            u64 qv = *reinterpret_cast<const u64*>(&kQv2[j * 4 + q]);
            u64 v = pfma(A[j][q], qi, MAG);
            v = psub(v, MAG);
            A[j][q] = pmul(v, qv);
        }
    }

    // Row IDCT.
#pragma unroll
    for (int c = 0; c < 4; c++)
        idct8p(A[0][c], A[1][c], A[2][c], A[3][c], A[4][c], A[5][c], A[6][c], A[7][c], K);

    repack(A);   // back to column-pair packing

    // Column IDCT.
#pragma unroll
    for (int c = 0; c < 4; c++)
        idct8p(A[0][c], A[1][c], A[2][c], A[3][c], A[4][c], A[5][c], A[6][c], A[7][c], K);

    // Store.
#pragma unroll
    for (int r = 0; r < 8; r++) {
        ulonglong2 a; a.x = A[r][0]; a.y = A[r][1];
        ulonglong2 b; b.x = A[r][2]; b.y = A[r][3];
        *reinterpret_cast<ulonglong2*>(qo + r * 512)     = a;
        *reinterpret_cast<ulonglong2*>(qo + r * 512 + 4) = b;
    }
}

extern "C" void kernel_launch(void* const* d_in, const int* in_sizes, int n_in,
                              void* d_out, int out_size) {
    const float* img = (const float*)d_in[0];
    float* out = (float*)d_out;
    diffjpeg_kernel<<<kNumBlocks / 128, 128>>>(img, out);
}